// round 14
// baseline (speedup 1.0000x reference)
#include <cuda_runtime.h>
#include <cuda_bf16.h>
#include <mma.h>
#include <cstdint>
#include <type_traits>

using namespace nvcuda;

#define B_  128
#define LC  256
#define LE  1024
#define D_  256
#define M_  512
#define NEGV (-1e9f)

typedef __nv_bfloat16 bf16;

// ---------------- scratch (device globals; no allocs allowed) ----------------
__device__ float g_align[(size_t)B_ * LC * LE];   // align (pre-softmax), fp32
__device__ float g_r1   [B_ * D_];
__device__ float g_r2   [B_ * D_];
__device__ bf16 g_crb  [(size_t)B_ * LC * D_];    // criteria bf16
__device__ bf16 g_ehb  [(size_t)B_ * LE * D_];    // ehr bf16
__device__ bf16 g_Wab  [D_ * D_];
__device__ bf16 g_Wrb  [2 * D_ * D_];
__device__ bf16 g_cb   [(size_t)B_ * LC * D_];    // relu(criteria@Wa+ba)
__device__ bf16 g_eb   [(size_t)B_ * LE * D_];    // relu(ehr@Wa+ba)
__device__ bf16 g_alb  [(size_t)B_ * LC * LE];    // alpha (Lc,Le)
__device__ bf16 g_bebT [(size_t)B_ * LE * LC];    // beta^T (Le,Lc)
__device__ bf16 g_atcb [(size_t)B_ * LC * D_];    // att_c
__device__ bf16 g_ateb [(size_t)B_ * LE * D_];    // att_e

__device__ __forceinline__ void cp_async16(void* smem_dst, const void* gsrc) {
    const uint32_t s = (uint32_t)__cvta_generic_to_shared(smem_dst);
    asm volatile("cp.async.cg.shared.global [%0], [%1], 16;\n" :: "r"(s), "l"(gsrc));
}
__device__ __forceinline__ void cp_commit() { asm volatile("cp.async.commit_group;\n"); }
__device__ __forceinline__ void cp_wait0()  { asm volatile("cp.async.wait_group 0;\n"); }
__device__ __forceinline__ void cp_wait1()  { asm volatile("cp.async.wait_group 1;\n"); }

// ---------------- fused conversions + accumulator zeroing ----------------
// Regions (in float4 units): criteria->crb, ehr->ehb, Wa->Wab, Wr->Wrb, zero r1|r2.
#define N4_CR   (B_*LC*D_/4)
#define N4_EH   (B_*LE*D_/4)
#define N4_WA   (D_*D_/4)
#define N4_WR   (2*D_*D_/4)
#define N4_RZ   (2*B_*D_/4)
#define N4_TOT  (N4_CR + N4_EH + N4_WA + N4_WR + N4_RZ)

__global__ __launch_bounds__(256)
void convert_all(const float* __restrict__ criteria, const float* __restrict__ ehr,
                 const float* __restrict__ Wa, const float* __restrict__ Wr,
                 bf16* __restrict__ crb, bf16* __restrict__ ehb,
                 bf16* __restrict__ Wab, bf16* __restrict__ Wrb,
                 float* __restrict__ r1)
{
    int i = blockIdx.x * 256 + threadIdx.x;
    if (i >= N4_TOT) return;
    const float* src;
    bf16* dst;
    if (i < N4_CR)                         { src = criteria; dst = crb; }
    else if ((i -= N4_CR) < N4_EH)         { src = ehr; dst = ehb; }
    else if ((i -= N4_EH) < N4_WA)         { src = Wa;  dst = Wab; }
    else if ((i -= N4_WA) < N4_WR)         { src = Wr;  dst = Wrb; }
    else {                                   // zero r1 then r2 (contiguous globals? no — use offset math)
        i -= N4_WR;
        ((float4*)r1)[i] = make_float4(0.f, 0.f, 0.f, 0.f);   // r1 and r2 passed as one span
        return;
    }
    const float4 v = ((const float4*)src)[i];
    __nv_bfloat162 lo = __floats2bfloat162_rn(v.x, v.y);
    __nv_bfloat162 hi = __floats2bfloat162_rn(v.z, v.w);
    uint2 o;
    o.x = *(uint32_t*)&lo; o.y = *(uint32_t*)&hi;
    ((uint2*)dst)[i] = o;
}

// ---------------- bf16 wmma GEMM: 128 threads, 4 warps, warp tile 64x64 --------
template <bool SPLITA, int TRANSB, bool OUT_BF16, bool BIAS_RELU, bool ROWSUM>
__global__ __launch_bounds__(128)
void bgemm(const bf16* __restrict__ A, const bf16* __restrict__ A2,
           const bf16* __restrict__ Bm, const float* __restrict__ bias,
           void* __restrict__ C,
           int K, int Ksplit,
           int lda, int ldb, int ldc,
           long long sA, long long sB, long long sC, int Lrows)
{
    constexpr int BM = 128, BN = 128, BK = 32, NS = 3;
    constexpr int A_LD = BK + 8;
    constexpr int ASZ  = BM * A_LD;
    constexpr int B_LD = (TRANSB == 1) ? (BK + 8) : (BN + 8);
    constexpr int BSZ  = (TRANSB == 1) ? BN * (BK + 8) : BK * (BN + 8);
    constexpr int STAGE = ASZ + BSZ;
    constexpr int C_LD = BN + 4;

    extern __shared__ __align__(16) char smraw[];
    bf16* smb = (bf16*)smraw;

    const int bz = blockIdx.z;
    const bf16* Ab = A  + (long long)bz * sA;
    const bf16* Bb = Bm + (long long)bz * sB;

    const int tid  = threadIdx.x;
    const int warp = tid >> 5;
    const int wm   = warp >> 1;
    const int wn   = warp & 1;
    const int m0   = blockIdx.x * BM;
    const int n0   = blockIdx.y * BN;

    using BLayout = typename std::conditional<TRANSB == 1, wmma::col_major, wmma::row_major>::type;

    wmma::fragment<wmma::accumulator, 16, 16, 16, float> acc[4][4];
    #pragma unroll
    for (int i = 0; i < 4; i++)
        #pragma unroll
        for (int j = 0; j < 4; j++)
            wmma::fill_fragment(acc[i][j], 0.0f);

    auto load_stage = [&](int s, int k0) {
        bf16* As = smb + s * STAGE;
        bf16* Bs = As + ASZ;
        const bf16* Asrc = Ab;
        int kk = k0;
        if (SPLITA && k0 >= Ksplit) { Asrc = A2; kk = k0 - Ksplit; }
        #pragma unroll
        for (int it = 0; it < 4; it++) {
            const int idx = tid + it * 128;
            const int r  = idx >> 2;
            const int kb = (idx & 3) * 8;
            cp_async16(&As[r * A_LD + kb], Asrc + (long long)(m0 + r) * lda + kk + kb);
        }
        #pragma unroll
        for (int it = 0; it < 4; it++) {
            const int idx = tid + it * 128;
            if (TRANSB == 1) {
                const int n  = idx >> 2;
                const int kb = (idx & 3) * 8;
                cp_async16(&Bs[n * B_LD + kb], Bb + (long long)(n0 + n) * ldb + k0 + kb);
            } else {
                const int k  = idx >> 4;
                const int nb = (idx & 15) * 8;
                cp_async16(&Bs[k * B_LD + nb], Bb + (long long)(k0 + k) * ldb + n0 + nb);
            }
        }
    };

    const int nT = K / BK;
    #pragma unroll
    for (int s = 0; s < NS - 1; s++) { load_stage(s, s * BK); cp_commit(); }

    for (int t = 0; t < nT; t++) {
        if (t + 1 < nT) cp_wait1(); else cp_wait0();
        __syncthreads();
        if (t + NS - 1 < nT) { load_stage((t + NS - 1) % NS, (t + NS - 1) * BK); cp_commit(); }

        const bf16* As = smb + (t % NS) * STAGE;
        const bf16* Bs = As + ASZ;
        #pragma unroll
        for (int kk = 0; kk < BK; kk += 16) {
            wmma::fragment<wmma::matrix_a, 16, 16, 16, bf16, wmma::row_major> afr[4];
            wmma::fragment<wmma::matrix_b, 16, 16, 16, bf16, BLayout> bfr[4];
            #pragma unroll
            for (int i = 0; i < 4; i++) {
                const int row = wm * 64 + i * 16;
                wmma::load_matrix_sync(afr[i], &As[row * A_LD + kk], A_LD);
            }
            #pragma unroll
            for (int j = 0; j < 4; j++) {
                const int col = wn * 64 + j * 16;
                const bf16* p = (TRANSB == 1) ? &Bs[col * B_LD + kk]
                                              : &Bs[kk * B_LD + col];
                wmma::load_matrix_sync(bfr[j], p, B_LD);
            }
            #pragma unroll
            for (int i = 0; i < 4; i++)
                #pragma unroll
                for (int j = 0; j < 4; j++)
                    wmma::mma_sync(acc[i][j], afr[i], bfr[j], acc[i][j]);
        }
        __syncthreads();
    }

    // ---- epilogue ----
    float* Cs = (float*)smraw;
    const int c4 = tid & 31;
    float4 bb = make_float4(0.f, 0.f, 0.f, 0.f);
    if (BIAS_RELU) bb = *(const float4*)&bias[n0 + c4 * 4];

    float csum[4] = {0.f, 0.f, 0.f, 0.f};

    #pragma unroll
    for (int phase = 0; phase < 2; phase++) {
        if (wm == phase) {
            #pragma unroll
            for (int i = 0; i < 4; i++)
                #pragma unroll
                for (int j = 0; j < 4; j++)
                    wmma::store_matrix_sync(&Cs[(i * 16) * C_LD + wn * 64 + j * 16],
                                            acc[i][j], C_LD, wmma::mem_row_major);
        }
        __syncthreads();
        #pragma unroll
        for (int it = 0; it < 16; it++) {
            const int idx = it * 128 + tid;
            const int r = idx >> 5;
            float4 v = *(float4*)&Cs[r * C_LD + c4 * 4];
            if (BIAS_RELU) {
                v.x = fmaxf(v.x + bb.x, 0.f); v.y = fmaxf(v.y + bb.y, 0.f);
                v.z = fmaxf(v.z + bb.z, 0.f); v.w = fmaxf(v.w + bb.w, 0.f);
            }
            if (ROWSUM) {
                csum[0] += v.x; csum[1] += v.y; csum[2] += v.z; csum[3] += v.w;
            } else {
                const long long row = (long long)(m0 + phase * 64 + r);
                if (OUT_BF16) {
                    bf16* Cb = (bf16*)C + (long long)bz * sC;
                    __nv_bfloat162 lo = __floats2bfloat162_rn(v.x, v.y);
                    __nv_bfloat162 hi = __floats2bfloat162_rn(v.z, v.w);
                    uint2 o; o.x = *(uint32_t*)&lo; o.y = *(uint32_t*)&hi;
                    *(uint2*)(Cb + row * ldc + n0 + c4 * 4) = o;
                } else {
                    float* Cb = (float*)C + (long long)bz * sC;
                    *(float4*)(Cb + row * ldc + n0 + c4 * 4) = v;
                }
            }
        }
        __syncthreads();
    }

    if (ROWSUM) {
        *(float4*)&Cs[tid * 4] = make_float4(csum[0], csum[1], csum[2], csum[3]);
        __syncthreads();
        if (tid < 32) {
            const int batch = m0 / Lrows;
            float* dst = (float*)C + batch * D_ + n0 + tid * 4;
            #pragma unroll
            for (int k = 0; k < 4; k++) {
                const float s = Cs[tid * 4 + k] + Cs[(tid + 32) * 4 + k]
                              + Cs[(tid + 64) * 4 + k] + Cs[(tid + 96) * 4 + k];
                atomicAdd(dst + k, s);
            }
        }
    }
}

// ---------------- masked softmax over Le (rows) -> bf16 alpha (shuffle reduce) ---
__global__ __launch_bounds__(256)
void softmax_rows(const float* __restrict__ align, const int* __restrict__ emask,
                  bf16* __restrict__ out)
{
    const int row = blockIdx.x;
    const int b = row >> 8;
    const float* a = align + (long long)row * LE;
    bf16* o = out + (long long)row * LE;
    const int* em = emask + b * LE;
    const int t = threadIdx.x;
    const int warp = t >> 5, lane = t & 31;
    __shared__ float part[8];

    float vals[4];
    float mx = -3.4e38f;
    #pragma unroll
    for (int i = 0; i < 4; i++) {
        const int e = t + i * 256;
        float v = a[e] + (1.0f - (float)em[e]) * NEGV;
        vals[i] = v;
        mx = fmaxf(mx, v);
    }
    #pragma unroll
    for (int off = 16; off > 0; off >>= 1)
        mx = fmaxf(mx, __shfl_xor_sync(0xFFFFFFFFu, mx, off));
    if (lane == 0) part[warp] = mx;
    __syncthreads();
    mx = part[0];
    #pragma unroll
    for (int w = 1; w < 8; w++) mx = fmaxf(mx, part[w]);
    __syncthreads();

    float sum = 0.f;
    #pragma unroll
    for (int i = 0; i < 4; i++) { vals[i] = __expf(vals[i] - mx); sum += vals[i]; }
    #pragma unroll
    for (int off = 16; off > 0; off >>= 1)
        sum += __shfl_xor_sync(0xFFFFFFFFu, sum, off);
    if (lane == 0) part[warp] = sum;
    __syncthreads();
    sum = part[0];
    #pragma unroll
    for (int w = 1; w < 8; w++) sum += part[w];

    const float inv = 1.0f / sum;
    #pragma unroll
    for (int i = 0; i < 4; i++) o[t + i * 256] = __float2bfloat16(vals[i] * inv);
}

// ---------------- masked softmax over Lc (cols) -> bf16 beta^T (Le,Lc) --------
__global__ __launch_bounds__(256)
void softmax_colsT(const float* __restrict__ align, const int* __restrict__ cmask,
                   bf16* __restrict__ outT)
{
    __shared__ float cmsk[LC];
    const int b = blockIdx.y;
    const int e = blockIdx.x * 256 + threadIdx.x;
    const float* a = align + (long long)b * LC * LE + e;
    bf16* o = outT + (long long)b * LE * LC + (long long)e * LC;
    const int* cm = cmask + b * LC;
    cmsk[threadIdx.x] = (1.0f - (float)cm[threadIdx.x]) * NEGV;
    __syncthreads();

    float mx = -3.4e38f, sum = 0.f;
    #pragma unroll 4
    for (int l = 0; l < LC; l++) {
        const float v = a[(long long)l * LE] + cmsk[l];
        if (v > mx) { sum = sum * __expf(mx - v); mx = v; }
        sum += __expf(v - mx);
    }
    const float inv = 1.0f / sum;
    for (int l0 = 0; l0 < LC; l0 += 8) {
        uint32_t pk[4];
        #pragma unroll
        for (int j = 0; j < 4; j++) {
            const float v0 = __expf(a[(long long)(l0 + 2*j    ) * LE] + cmsk[l0 + 2*j    ] - mx) * inv;
            const float v1 = __expf(a[(long long)(l0 + 2*j + 1) * LE] + cmsk[l0 + 2*j + 1] - mx) * inv;
            __nv_bfloat162 h = __floats2bfloat162_rn(v0, v1);
            pk[j] = *(uint32_t*)&h;
        }
        *(uint4*)(o + l0) = make_uint4(pk[0], pk[1], pk[2], pk[3]);
    }
}

// ---------------- final MLP: one block per batch ----------------
__global__ __launch_bounds__(256)
void final_mlp(const float* __restrict__ r1, const float* __restrict__ r2,
               const float* __restrict__ Wm, const float* __restrict__ bm,
               const float* __restrict__ Wo, const float* __restrict__ bo,
               float* __restrict__ out)
{
    const int b = blockIdx.x;
    const int t = threadIdx.x;
    __shared__ float m[4 * D_];
    __shared__ float h[M_];

    const float a = r1[b * D_ + t];
    const float c = r2[b * D_ + t];
    m[t] = a; m[D_ + t] = c; m[2 * D_ + t] = a * c; m[3 * D_ + t] = a - c;
    __syncthreads();

    for (int j = t; j < M_; j += 256) {
        float s = bm[j];
        #pragma unroll 8
        for (int k = 0; k < 4 * D_; k++) s += m[k] * Wm[k * M_ + j];
        h[j] = fmaxf(s, 0.f);
    }
    __syncthreads();

    float p0 = 0.f, p1 = 0.f, p2 = 0.f;
    for (int j = t; j < M_; j += 256) {
        const float hv = h[j];
        p0 += hv * Wo[j * 3 + 0];
        p1 += hv * Wo[j * 3 + 1];
        p2 += hv * Wo[j * 3 + 2];
    }
    __shared__ float red[3][256];
    red[0][t] = p0; red[1][t] = p1; red[2][t] = p2; __syncthreads();
    for (int s = 128; s > 0; s >>= 1) {
        if (t < s) {
            red[0][t] += red[0][t + s];
            red[1][t] += red[1][t + s];
            red[2][t] += red[2][t + s];
        }
        __syncthreads();
    }
    if (t < 3) out[b * 3 + t] = red[t][0] + bo[t];
}

// ---------------- host launcher ----------------
static const int GSMEM = 62 * 1024;

extern "C" void kernel_launch(void* const* d_in, const int* in_sizes, int n_in,
                              void* d_out, int out_size)
{
    const float *criteria = nullptr, *ehr = nullptr, *Wa = nullptr, *ba = nullptr,
                *Wr = nullptr, *br = nullptr, *Wm = nullptr, *bm = nullptr,
                *Wo = nullptr, *bo = nullptr;
    const int *cmask = nullptr, *emask = nullptr;

    for (int i = 0; i < n_in; i++) {
        const int s = in_sizes[i];
        switch (s) {
            case 8388608:  criteria = (const float*)d_in[i]; break;
            case 33554432: ehr      = (const float*)d_in[i]; break;
            case 32768:    cmask    = (const int*)d_in[i];   break;
            case 65536:    Wa       = (const float*)d_in[i]; break;
            case 524288:   Wm       = (const float*)d_in[i]; break;
            case 512:      bm       = (const float*)d_in[i]; break;
            case 1536:     Wo       = (const float*)d_in[i]; break;
            case 3:        bo       = (const float*)d_in[i]; break;
            case 131072: {
                const int prev = (i > 0) ? in_sizes[i - 1] : -1;
                if (prev == 256) Wr = (const float*)d_in[i];
                else             emask = (const int*)d_in[i];
                break;
            }
            case 256: {
                const int nxt = (i + 1 < n_in) ? in_sizes[i + 1] : -1;
                if (nxt == 131072) ba = (const float*)d_in[i];
                else               br = (const float*)d_in[i];
                break;
            }
            default: break;
        }
    }

    // one-time setup on the (uncaptured) correctness call
    static bool init_done = false;
    static cudaStream_t s1;
    static cudaEvent_t evConv, evG1, evFork, evJoin;
    if (!init_done) {
        cudaStreamCreateWithFlags(&s1, cudaStreamNonBlocking);
        cudaEventCreateWithFlags(&evConv, cudaEventDisableTiming);
        cudaEventCreateWithFlags(&evG1,   cudaEventDisableTiming);
        cudaEventCreateWithFlags(&evFork, cudaEventDisableTiming);
        cudaEventCreateWithFlags(&evJoin, cudaEventDisableTiming);
        cudaFuncSetAttribute(bgemm<false,0,true,true,false>,  cudaFuncAttributeMaxDynamicSharedMemorySize, GSMEM);
        cudaFuncSetAttribute(bgemm<false,1,false,false,false>,cudaFuncAttributeMaxDynamicSharedMemorySize, GSMEM);
        cudaFuncSetAttribute(bgemm<false,0,true,false,false>, cudaFuncAttributeMaxDynamicSharedMemorySize, GSMEM);
        cudaFuncSetAttribute(bgemm<true,0,false,true,true>,   cudaFuncAttributeMaxDynamicSharedMemorySize, GSMEM);
        init_done = true;
    }

    float *al_, *r1_, *r2_;
    bf16 *crb, *ehb, *Wab, *Wrb, *cb, *eb, *alb, *bebT, *atcb, *ateb;
    cudaGetSymbolAddress((void**)&al_,  g_align);
    cudaGetSymbolAddress((void**)&r1_,  g_r1);
    cudaGetSymbolAddress((void**)&r2_,  g_r2);
    cudaGetSymbolAddress((void**)&crb,  g_crb);
    cudaGetSymbolAddress((void**)&ehb,  g_ehb);
    cudaGetSymbolAddress((void**)&Wab,  g_Wab);
    cudaGetSymbolAddress((void**)&Wrb,  g_Wrb);
    cudaGetSymbolAddress((void**)&cb,   g_cb);
    cudaGetSymbolAddress((void**)&eb,   g_eb);
    cudaGetSymbolAddress((void**)&alb,  g_alb);
    cudaGetSymbolAddress((void**)&bebT, g_bebT);
    cudaGetSymbolAddress((void**)&atcb, g_atcb);
    cudaGetSymbolAddress((void**)&ateb, g_ateb);

    const dim3 blk(128);

    // 0) fused conversions + zero r1/r2 (r1,r2 contiguous? NO — zero r1 span only covers r1;
    //    g_r1 and g_r2 are separate symbols; pass r1_ and r2_ zeroed via two regions:
    //    region 5 covers 2*B*D/4 float4 = r1 then r2 — they are distinct allocations, so
    //    split the zeroing: first half -> r1, second half -> r2 inside the kernel would need
    //    both pointers; simplest: memsets here (graph-legal) + smaller convert kernel.
    convert_all<<<(N4_CR + N4_EH + N4_WA + N4_WR + 255) / 256 + 1, 256>>>(
        criteria, ehr, Wa, Wr, crb, ehb, Wab, Wrb, r1_);
    cudaMemsetAsync(r1_, 0, B_ * D_ * sizeof(float));
    cudaMemsetAsync(r2_, 0, B_ * D_ * sizeof(float));
    cudaEventRecord(evConv, 0);

    // fork: GEMM1 on s1 concurrent with GEMM2 on s0
    cudaStreamWaitEvent(s1, evConv, 0);
    bgemm<false,0,true,true,false><<<dim3(256, 2, 1), blk, GSMEM, s1>>>(
        crb, nullptr, Wab, ba, cb, D_, 0, D_, D_, D_, 0, 0, 0, 0);
    cudaEventRecord(evG1, s1);

    bgemm<false,0,true,true,false><<<dim3(1024, 2, 1), blk, GSMEM>>>(
        ehb, nullptr, Wab, ba, eb, D_, 0, D_, D_, D_, 0, 0, 0, 0);
    cudaStreamWaitEvent(0, evG1, 0);

    // 3) align[b] = c[b] @ e[b]^T -> fp32
    bgemm<false,1,false,false,false><<<dim3(2, 8, B_), blk, GSMEM>>>(
        cb, nullptr, eb, nullptr, al_, D_, 0, D_, D_, LE,
        (long long)LC * D_, (long long)LE * D_, (long long)LC * LE, 0);
    cudaEventRecord(evFork, 0);

    // chain A (s0): alpha -> att_c -> r1
    softmax_rows<<<B_ * LC, 256>>>(al_, emask, alb);
    bgemm<false,0,true,false,false><<<dim3(2, 2, B_), blk, GSMEM>>>(
        alb, nullptr, ehb, nullptr, atcb, LE, 0, LE, D_, D_,
        (long long)LC * LE, (long long)LE * D_, (long long)LC * D_, 0);
    bgemm<true,0,false,true,true><<<dim3(256, 2, 1), blk, GSMEM>>>(
        atcb, crb, Wrb, br, r1_, 2 * D_, D_, D_, D_, LC, 0, 0, 0, LC);

    // chain B (s1): beta^T -> att_e -> r2
    cudaStreamWaitEvent(s1, evFork, 0);
    softmax_colsT<<<dim3(LE / 256, B_), 256, 0, s1>>>(al_, cmask, bebT);
    bgemm<false,0,true,false,false><<<dim3(8, 2, B_), blk, GSMEM, s1>>>(
        bebT, nullptr, crb, nullptr, ateb, LC, 0, LC, D_, D_,
        (long long)LE * LC, (long long)LC * D_, (long long)LE * D_, 0);
    bgemm<true,0,false,true,true><<<dim3(1024, 2, 1), blk, GSMEM, s1>>>(
        ateb, ehb, Wrb, br, r2_, 2 * D_, D_, D_, D_, LE, 0, 0, 0, LE);
    cudaEventRecord(evJoin, s1);

    // join + final MLP
    cudaStreamWaitEvent(0, evJoin, 0);
    final_mlp<<<B_, 256>>>(r1_, r2_, Wm, bm, Wo, bo, (float*)d_out);
}

// round 15
// speedup vs baseline: 1.3919x; 1.3919x over previous
#include <cuda_runtime.h>
#include <cuda_bf16.h>
#include <mma.h>
#include <cstdint>
#include <type_traits>

using namespace nvcuda;

#define B_  128
#define LC  256
#define LE  1024
#define D_  256
#define M_  512
#define NEGV (-1e9f)

typedef __nv_bfloat16 bf16;

// ---------------- scratch (device globals; no allocs allowed) ----------------
__device__ float g_align[(size_t)B_ * LC * LE];   // align (pre-softmax), fp32
__device__ float g_r1   [B_ * D_];
__device__ float g_r2   [B_ * D_];
__device__ bf16 g_crb  [(size_t)B_ * LC * D_];    // criteria bf16
__device__ bf16 g_ehb  [(size_t)B_ * LE * D_];    // ehr bf16
__device__ bf16 g_Wab  [D_ * D_];
__device__ bf16 g_Wrb  [2 * D_ * D_];
__device__ bf16 g_cb   [(size_t)B_ * LC * D_];    // relu(criteria@Wa+ba)
__device__ bf16 g_eb   [(size_t)B_ * LE * D_];    // relu(ehr@Wa+ba)
__device__ bf16 g_alb  [(size_t)B_ * LC * LE];    // alpha (Lc,Le)
__device__ bf16 g_bebT [(size_t)B_ * LE * LC];    // beta^T (Le,Lc)
__device__ bf16 g_atcb [(size_t)B_ * LC * D_];    // att_c
__device__ bf16 g_ateb [(size_t)B_ * LE * D_];    // att_e

__device__ __forceinline__ void cp_async16(void* smem_dst, const void* gsrc) {
    const uint32_t s = (uint32_t)__cvta_generic_to_shared(smem_dst);
    asm volatile("cp.async.cg.shared.global [%0], [%1], 16;\n" :: "r"(s), "l"(gsrc));
}
__device__ __forceinline__ void cp_commit() { asm volatile("cp.async.commit_group;\n"); }
__device__ __forceinline__ void cp_wait0()  { asm volatile("cp.async.wait_group 0;\n"); }

// ---------------- fused conversions ----------------
#define N4_CR   (B_*LC*D_/4)
#define N4_EH   (B_*LE*D_/4)
#define N4_WA   (D_*D_/4)
#define N4_WR   (2*D_*D_/4)
#define N4_TOT  (N4_CR + N4_EH + N4_WA + N4_WR)

__global__ __launch_bounds__(256)
void convert_all(const float* __restrict__ criteria, const float* __restrict__ ehr,
                 const float* __restrict__ Wa, const float* __restrict__ Wr,
                 bf16* __restrict__ crb, bf16* __restrict__ ehb,
                 bf16* __restrict__ Wab, bf16* __restrict__ Wrb)
{
    int i = blockIdx.x * 256 + threadIdx.x;
    if (i >= N4_TOT) return;
    const float* src;
    bf16* dst;
    if (i < N4_CR)                 { src = criteria; dst = crb; }
    else if ((i -= N4_CR) < N4_EH) { src = ehr; dst = ehb; }
    else if ((i -= N4_EH) < N4_WA) { src = Wa;  dst = Wab; }
    else { i -= N4_WA;               src = Wr;  dst = Wrb; }
    const float4 v = ((const float4*)src)[i];
    __nv_bfloat162 lo = __floats2bfloat162_rn(v.x, v.y);
    __nv_bfloat162 hi = __floats2bfloat162_rn(v.z, v.w);
    uint2 o;
    o.x = *(uint32_t*)&lo; o.y = *(uint32_t*)&hi;
    ((uint2*)dst)[i] = o;
}

// ---------------- bf16 wmma GEMM: 128 threads, 4 warps, 64x64 warp tile --------
// BK=64, 2-stage cp.async (wait0 pattern).
template <bool SPLITA, int TRANSB, bool OUT_BF16, bool BIAS_RELU, bool ROWSUM>
__global__ __launch_bounds__(128)
void bgemm(const bf16* __restrict__ A, const bf16* __restrict__ A2,
           const bf16* __restrict__ Bm, const float* __restrict__ bias,
           void* __restrict__ C,
           int K, int Ksplit,
           int lda, int ldb, int ldc,
           long long sA, long long sB, long long sC, int Lrows)
{
    constexpr int BM = 128, BN = 128, BK = 64;
    constexpr int A_LD = BK + 8;                                // 72
    constexpr int ASZ  = BM * A_LD;                             // 9216
    constexpr int B_LD = (TRANSB == 1) ? (BK + 8) : (BN + 8);   // 72 : 136
    constexpr int BSZ  = (TRANSB == 1) ? BN * (BK + 8) : BK * (BN + 8);
    constexpr int STAGE = ASZ + BSZ;                            // bf16 elements
    constexpr int C_LD = BN + 4;

    extern __shared__ __align__(16) char smraw[];
    bf16* smb = (bf16*)smraw;

    const int bz = blockIdx.z;
    const bf16* Ab = A  + (long long)bz * sA;
    const bf16* Bb = Bm + (long long)bz * sB;

    const int tid  = threadIdx.x;
    const int warp = tid >> 5;
    const int wm   = warp >> 1;
    const int wn   = warp & 1;
    const int m0   = blockIdx.x * BM;
    const int n0   = blockIdx.y * BN;

    using BLayout = typename std::conditional<TRANSB == 1, wmma::col_major, wmma::row_major>::type;

    wmma::fragment<wmma::accumulator, 16, 16, 16, float> acc[4][4];
    #pragma unroll
    for (int i = 0; i < 4; i++)
        #pragma unroll
        for (int j = 0; j < 4; j++)
            wmma::fill_fragment(acc[i][j], 0.0f);

    auto load_stage = [&](int s, int k0) {
        bf16* As = smb + s * STAGE;
        bf16* Bs = As + ASZ;
        const bf16* Asrc = Ab;
        int kk = k0;
        if (SPLITA && k0 >= Ksplit) { Asrc = A2; kk = k0 - Ksplit; }
        #pragma unroll
        for (int it = 0; it < 8; it++) {            // A: 1024 chunks of 16B
            const int idx = tid + it * 128;
            const int r  = idx >> 3;                // 0..127
            const int kb = (idx & 7) * 8;           // 0..56
            cp_async16(&As[r * A_LD + kb], Asrc + (long long)(m0 + r) * lda + kk + kb);
        }
        #pragma unroll
        for (int it = 0; it < 8; it++) {            // B: 1024 chunks of 16B
            const int idx = tid + it * 128;
            if (TRANSB == 1) {
                const int n  = idx >> 3;            // 0..127
                const int kb = (idx & 7) * 8;
                cp_async16(&Bs[n * B_LD + kb], Bb + (long long)(n0 + n) * ldb + k0 + kb);
            } else {
                const int k  = idx >> 4;            // 0..63
                const int nb = (idx & 15) * 8;
                cp_async16(&Bs[k * B_LD + nb], Bb + (long long)(k0 + k) * ldb + n0 + nb);
            }
        }
    };

    const int nT = K / BK;
    load_stage(0, 0); cp_commit();

    for (int t = 0; t < nT; t++) {
        cp_wait0();
        __syncthreads();
        if (t + 1 < nT) { load_stage((t + 1) & 1, (t + 1) * BK); cp_commit(); }

        const bf16* As = smb + (t & 1) * STAGE;
        const bf16* Bs = As + ASZ;
        #pragma unroll
        for (int kk = 0; kk < BK; kk += 16) {
            wmma::fragment<wmma::matrix_a, 16, 16, 16, bf16, wmma::row_major> afr[4];
            wmma::fragment<wmma::matrix_b, 16, 16, 16, bf16, BLayout> bfr[4];
            #pragma unroll
            for (int i = 0; i < 4; i++) {
                const int row = wm * 64 + i * 16;
                wmma::load_matrix_sync(afr[i], &As[row * A_LD + kk], A_LD);
            }
            #pragma unroll
            for (int j = 0; j < 4; j++) {
                const int col = wn * 64 + j * 16;
                const bf16* p = (TRANSB == 1) ? &Bs[col * B_LD + kk]
                                              : &Bs[kk * B_LD + col];
                wmma::load_matrix_sync(bfr[j], p, B_LD);
            }
            #pragma unroll
            for (int i = 0; i < 4; i++)
                #pragma unroll
                for (int j = 0; j < 4; j++)
                    wmma::mma_sync(acc[i][j], afr[i], bfr[j], acc[i][j]);
        }
        __syncthreads();
    }

    // ---- epilogue: 2 phases of 64 rows via fp32 smem staging ----
    float* Cs = (float*)smraw;
    const int c4 = tid & 31;
    float4 bb = make_float4(0.f, 0.f, 0.f, 0.f);
    if (BIAS_RELU) bb = *(const float4*)&bias[n0 + c4 * 4];

    float csum[4] = {0.f, 0.f, 0.f, 0.f};

    #pragma unroll
    for (int phase = 0; phase < 2; phase++) {
        if (wm == phase) {
            #pragma unroll
            for (int i = 0; i < 4; i++)
                #pragma unroll
                for (int j = 0; j < 4; j++)
                    wmma::store_matrix_sync(&Cs[(i * 16) * C_LD + wn * 64 + j * 16],
                                            acc[i][j], C_LD, wmma::mem_row_major);
        }
        __syncthreads();
        #pragma unroll
        for (int it = 0; it < 16; it++) {
            const int idx = it * 128 + tid;
            const int r = idx >> 5;
            float4 v = *(float4*)&Cs[r * C_LD + c4 * 4];
            if (BIAS_RELU) {
                v.x = fmaxf(v.x + bb.x, 0.f); v.y = fmaxf(v.y + bb.y, 0.f);
                v.z = fmaxf(v.z + bb.z, 0.f); v.w = fmaxf(v.w + bb.w, 0.f);
            }
            if (ROWSUM) {
                csum[0] += v.x; csum[1] += v.y; csum[2] += v.z; csum[3] += v.w;
            } else {
                const long long row = (long long)(m0 + phase * 64 + r);
                if (OUT_BF16) {
                    bf16* Cb = (bf16*)C + (long long)bz * sC;
                    __nv_bfloat162 lo = __floats2bfloat162_rn(v.x, v.y);
                    __nv_bfloat162 hi = __floats2bfloat162_rn(v.z, v.w);
                    uint2 o; o.x = *(uint32_t*)&lo; o.y = *(uint32_t*)&hi;
                    *(uint2*)(Cb + row * ldc + n0 + c4 * 4) = o;
                } else {
                    float* Cb = (float*)C + (long long)bz * sC;
                    *(float4*)(Cb + row * ldc + n0 + c4 * 4) = v;
                }
            }
        }
        __syncthreads();
    }

    if (ROWSUM) {
        *(float4*)&Cs[tid * 4] = make_float4(csum[0], csum[1], csum[2], csum[3]);
        __syncthreads();
        if (tid < 32) {
            const int batch = m0 / Lrows;
            float* dst = (float*)C + batch * D_ + n0 + tid * 4;
            #pragma unroll
            for (int k = 0; k < 4; k++) {
                const float s = Cs[tid * 4 + k] + Cs[(tid + 32) * 4 + k]
                              + Cs[(tid + 64) * 4 + k] + Cs[(tid + 96) * 4 + k];
                atomicAdd(dst + k, s);
            }
        }
    }
}

// ---------------- masked softmax over Le (rows) -> bf16 alpha (shuffle reduce) ---
__global__ __launch_bounds__(256)
void softmax_rows(const float* __restrict__ align, const int* __restrict__ emask,
                  bf16* __restrict__ out)
{
    const int row = blockIdx.x;
    const int b = row >> 8;
    const float* a = align + (long long)row * LE;
    bf16* o = out + (long long)row * LE;
    const int* em = emask + b * LE;
    const int t = threadIdx.x;
    const int warp = t >> 5, lane = t & 31;
    __shared__ float part[8];

    float vals[4];
    float mx = -3.4e38f;
    #pragma unroll
    for (int i = 0; i < 4; i++) {
        const int e = t + i * 256;
        float v = a[e] + (1.0f - (float)em[e]) * NEGV;
        vals[i] = v;
        mx = fmaxf(mx, v);
    }
    #pragma unroll
    for (int off = 16; off > 0; off >>= 1)
        mx = fmaxf(mx, __shfl_xor_sync(0xFFFFFFFFu, mx, off));
    if (lane == 0) part[warp] = mx;
    __syncthreads();
    mx = part[0];
    #pragma unroll
    for (int w = 1; w < 8; w++) mx = fmaxf(mx, part[w]);
    __syncthreads();

    float sum = 0.f;
    #pragma unroll
    for (int i = 0; i < 4; i++) { vals[i] = __expf(vals[i] - mx); sum += vals[i]; }
    #pragma unroll
    for (int off = 16; off > 0; off >>= 1)
        sum += __shfl_xor_sync(0xFFFFFFFFu, sum, off);
    if (lane == 0) part[warp] = sum;
    __syncthreads();
    sum = part[0];
    #pragma unroll
    for (int w = 1; w < 8; w++) sum += part[w];

    const float inv = 1.0f / sum;
    #pragma unroll
    for (int i = 0; i < 4; i++) o[t + i * 256] = __float2bfloat16(vals[i] * inv);
}

// ---------------- masked softmax over Lc (cols) -> bf16 beta^T (Le,Lc) --------
__global__ __launch_bounds__(256)
void softmax_colsT(const float* __restrict__ align, const int* __restrict__ cmask,
                   bf16* __restrict__ outT)
{
    __shared__ float cmsk[LC];
    const int b = blockIdx.y;
    const int e = blockIdx.x * 256 + threadIdx.x;
    const float* a = align + (long long)b * LC * LE + e;
    bf16* o = outT + (long long)b * LE * LC + (long long)e * LC;
    const int* cm = cmask + b * LC;
    cmsk[threadIdx.x] = (1.0f - (float)cm[threadIdx.x]) * NEGV;
    __syncthreads();

    float mx = -3.4e38f, sum = 0.f;
    #pragma unroll 4
    for (int l = 0; l < LC; l++) {
        const float v = a[(long long)l * LE] + cmsk[l];
        if (v > mx) { sum = sum * __expf(mx - v); mx = v; }
        sum += __expf(v - mx);
    }
    const float inv = 1.0f / sum;
    for (int l0 = 0; l0 < LC; l0 += 8) {
        uint32_t pk[4];
        #pragma unroll
        for (int j = 0; j < 4; j++) {
            const float v0 = __expf(a[(long long)(l0 + 2*j    ) * LE] + cmsk[l0 + 2*j    ] - mx) * inv;
            const float v1 = __expf(a[(long long)(l0 + 2*j + 1) * LE] + cmsk[l0 + 2*j + 1] - mx) * inv;
            __nv_bfloat162 h = __floats2bfloat162_rn(v0, v1);
            pk[j] = *(uint32_t*)&h;
        }
        *(uint4*)(o + l0) = make_uint4(pk[0], pk[1], pk[2], pk[3]);
    }
}

// ---------------- final MLP: one block per batch ----------------
__global__ __launch_bounds__(256)
void final_mlp(const float* __restrict__ r1, const float* __restrict__ r2,
               const float* __restrict__ Wm, const float* __restrict__ bm,
               const float* __restrict__ Wo, const float* __restrict__ bo,
               float* __restrict__ out)
{
    const int b = blockIdx.x;
    const int t = threadIdx.x;
    __shared__ float m[4 * D_];
    __shared__ float h[M_];

    const float a = r1[b * D_ + t];
    const float c = r2[b * D_ + t];
    m[t] = a; m[D_ + t] = c; m[2 * D_ + t] = a * c; m[3 * D_ + t] = a - c;
    __syncthreads();

    for (int j = t; j < M_; j += 256) {
        float s = bm[j];
        #pragma unroll 8
        for (int k = 0; k < 4 * D_; k++) s += m[k] * Wm[k * M_ + j];
        h[j] = fmaxf(s, 0.f);
    }
    __syncthreads();

    float p0 = 0.f, p1 = 0.f, p2 = 0.f;
    for (int j = t; j < M_; j += 256) {
        const float hv = h[j];
        p0 += hv * Wo[j * 3 + 0];
        p1 += hv * Wo[j * 3 + 1];
        p2 += hv * Wo[j * 3 + 2];
    }
    __shared__ float red[3][256];
    red[0][t] = p0; red[1][t] = p1; red[2][t] = p2; __syncthreads();
    for (int s = 128; s > 0; s >>= 1) {
        if (t < s) {
            red[0][t] += red[0][t + s];
            red[1][t] += red[1][t + s];
            red[2][t] += red[2][t + s];
        }
        __syncthreads();
    }
    if (t < 3) out[b * 3 + t] = red[t][0] + bo[t];
}

// ---------------- host launcher ----------------
static const int GSMEM = 74 * 1024;

extern "C" void kernel_launch(void* const* d_in, const int* in_sizes, int n_in,
                              void* d_out, int out_size)
{
    const float *criteria = nullptr, *ehr = nullptr, *Wa = nullptr, *ba = nullptr,
                *Wr = nullptr, *br = nullptr, *Wm = nullptr, *bm = nullptr,
                *Wo = nullptr, *bo = nullptr;
    const int *cmask = nullptr, *emask = nullptr;

    for (int i = 0; i < n_in; i++) {
        const int s = in_sizes[i];
        switch (s) {
            case 8388608:  criteria = (const float*)d_in[i]; break;
            case 33554432: ehr      = (const float*)d_in[i]; break;
            case 32768:    cmask    = (const int*)d_in[i];   break;
            case 65536:    Wa       = (const float*)d_in[i]; break;
            case 524288:   Wm       = (const float*)d_in[i]; break;
            case 512:      bm       = (const float*)d_in[i]; break;
            case 1536:     Wo       = (const float*)d_in[i]; break;
            case 3:        bo       = (const float*)d_in[i]; break;
            case 131072: {
                const int prev = (i > 0) ? in_sizes[i - 1] : -1;
                if (prev == 256) Wr = (const float*)d_in[i];
                else             emask = (const int*)d_in[i];
                break;
            }
            case 256: {
                const int nxt = (i + 1 < n_in) ? in_sizes[i + 1] : -1;
                if (nxt == 131072) ba = (const float*)d_in[i];
                else               br = (const float*)d_in[i];
                break;
            }
            default: break;
        }
    }

    cudaFuncSetAttribute(bgemm<false,0,true,true,false>,  cudaFuncAttributeMaxDynamicSharedMemorySize, GSMEM);
    cudaFuncSetAttribute(bgemm<false,1,false,false,false>,cudaFuncAttributeMaxDynamicSharedMemorySize, GSMEM);
    cudaFuncSetAttribute(bgemm<false,0,true,false,false>, cudaFuncAttributeMaxDynamicSharedMemorySize, GSMEM);
    cudaFuncSetAttribute(bgemm<true,0,false,true,true>,   cudaFuncAttributeMaxDynamicSharedMemorySize, GSMEM);

    float *al_, *r1_, *r2_;
    bf16 *crb, *ehb, *Wab, *Wrb, *cb, *eb, *alb, *bebT, *atcb, *ateb;
    cudaGetSymbolAddress((void**)&al_,  g_align);
    cudaGetSymbolAddress((void**)&r1_,  g_r1);
    cudaGetSymbolAddress((void**)&r2_,  g_r2);
    cudaGetSymbolAddress((void**)&crb,  g_crb);
    cudaGetSymbolAddress((void**)&ehb,  g_ehb);
    cudaGetSymbolAddress((void**)&Wab,  g_Wab);
    cudaGetSymbolAddress((void**)&Wrb,  g_Wrb);
    cudaGetSymbolAddress((void**)&cb,   g_cb);
    cudaGetSymbolAddress((void**)&eb,   g_eb);
    cudaGetSymbolAddress((void**)&alb,  g_alb);
    cudaGetSymbolAddress((void**)&bebT, g_bebT);
    cudaGetSymbolAddress((void**)&atcb, g_atcb);
    cudaGetSymbolAddress((void**)&ateb, g_ateb);

    const dim3 blk(128);

    // 0) fused conversions + zero accumulators
    convert_all<<<(N4_TOT + 255) / 256, 256>>>(criteria, ehr, Wa, Wr, crb, ehb, Wab, Wrb);
    cudaMemsetAsync(r1_, 0, B_ * D_ * sizeof(float));
    cudaMemsetAsync(r2_, 0, B_ * D_ * sizeof(float));

    // 1) c = relu(criteria@Wa+ba) -> bf16
    bgemm<false,0,true,true,false><<<dim3(256, 2, 1), blk, GSMEM>>>(
        crb, nullptr, Wab, ba, cb, D_, 0, D_, D_, D_, 0, 0, 0, 0);
    // 2) e = relu(ehr@Wa+ba) -> bf16
    bgemm<false,0,true,true,false><<<dim3(1024, 2, 1), blk, GSMEM>>>(
        ehb, nullptr, Wab, ba, eb, D_, 0, D_, D_, D_, 0, 0, 0, 0);
    // 3) align[b] = c[b] @ e[b]^T -> fp32, batched
    bgemm<false,1,false,false,false><<<dim3(2, 8, B_), blk, GSMEM>>>(
        cb, nullptr, eb, nullptr, al_, D_, 0, D_, D_, LE,
        (long long)LC * D_, (long long)LE * D_, (long long)LC * LE, 0);
    // 4) alpha = softmax over Le (rows) -> bf16 (Lc,Le)
    softmax_rows<<<B_ * LC, 256>>>(al_, emask, alb);
    // 5) beta^T = softmax over Lc (cols) -> bf16 (Le,Lc)
    softmax_colsT<<<dim3(LE / 256, B_), 256>>>(al_, cmask, bebT);
    // 6) att_c[b] = alpha[b] @ ehr[b] -> bf16
    bgemm<false,0,true,false,false><<<dim3(2, 2, B_), blk, GSMEM>>>(
        alb, nullptr, ehb, nullptr, atcb, LE, 0, LE, D_, D_,
        (long long)LC * LE, (long long)LE * D_, (long long)LC * D_, 0);
    // 7) att_e[b] = beta^T[b] @ criteria[b] -> bf16
    bgemm<false,0,true,false,false><<<dim3(8, 2, B_), blk, GSMEM>>>(
        bebT, nullptr, crb, nullptr, ateb, LC, 0, LC, D_, D_,
        (long long)LE * LC, (long long)LC * D_, (long long)LE * D_, 0);
    // 8) r1 += rowsum(relu([att_c|criteria]@Wr+br)); Lrows=LC
    bgemm<true,0,false,true,true><<<dim3(256, 2, 1), blk, GSMEM>>>(
        atcb, crb, Wrb, br, r1_, 2 * D_, D_, D_, D_, LC, 0, 0, 0, LC);
    // 9) r2 += rowsum(relu([att_e|ehr]@Wr+br)); Lrows=LE
    bgemm<true,0,false,true,true><<<dim3(1024, 2, 1), blk, GSMEM>>>(
        ateb, ehb, Wrb, br, r2_, 2 * D_, D_, D_, D_, LE, 0, 0, 0, LE);
    // 10) final MLP -> (B, 3)
    final_mlp<<<B_, 256>>>(r1_, r2_, Wm, bm, Wo, bo, (float*)d_out);
}